// round 4
// baseline (speedup 1.0000x reference)
#include <cuda_runtime.h>
#include <cuda_bf16.h>
#include <cstdint>
#include <cstddef>

// Problem dims
#define TT 2048
#define NB 32
#define UU 256
// out = [32,2048,512] then states hf,cf,hb,cb each [32,256]
#define OUT_MAIN ((size_t)NB * TT * 512)
#define OUT_FULL (OUT_MAIN + 4 * (size_t)NB * UU)

// ---------------- static device scratch ----------------
__device__ float g_xz[(size_t)TT * NB * 2048];   // [t*32+b][2048] gate preacts (fwd 0..1023, bwd 1024..2047)
__device__ float g_X1[(size_t)TT * NB * 512];    // layer0 output [t][b][512]
__device__ float g_X2[(size_t)TT * NB * 512];    // layer1 output
__device__ float g_Ure[3][2][UU * 1024];         // [layer][dir][k][u*4+g]
__device__ float g_Wcat[2][512 * 2048];          // [l][k][d*1024 + u*4+g]
__device__ float g_bcat[2][2048];
__device__ float g_W0re[2][1024];                // [d][u*4+g]
__device__ float g_b0re[2][1024];
__device__ float g_hbuf[2][2][UU * NB];          // [phase][dir][u*32+b]
__device__ float g_stateH[2][UU * NB];           // [dir][u*32+b]
__device__ float g_stateC[2][UU * NB];
__device__ unsigned g_cnt[2];

// ---------------- packed f32x2 helpers ----------------
__device__ __forceinline__ void fma2(unsigned long long& d, unsigned long long a,
                                     unsigned long long b) {
    asm("fma.rn.f32x2 %0, %1, %2, %0;" : "+l"(d) : "l"(a), "l"(b));
}
__device__ __forceinline__ unsigned long long pack2(float x) {
    unsigned long long r;
    asm("mov.b64 %0, {%1, %1};" : "=l"(r) : "f"(x));
    return r;
}
__device__ __forceinline__ unsigned long long pack2b(float x, float y) {
    unsigned long long r;
    asm("mov.b64 %0, {%1, %2};" : "=l"(r) : "f"(x), "f"(y));
    return r;
}
__device__ __forceinline__ float2 unpack2(unsigned long long v) {
    float2 f;
    asm("mov.b64 {%0, %1}, %2;" : "=f"(f.x), "=f"(f.y) : "l"(v));
    return f;
}

// ---------------- fast-math-immune activations ----------------
// Precise expf: rintf + 2-part ln2 reduction + deg-7 Taylor, all fmaf (exact
// under --use_fast_math). Truncation ~5e-9 rel.
__device__ __forceinline__ float exp_p(float x) {
    float t = fminf(fmaxf(x, -87.0f), 87.0f);
    float n = rintf(t * 1.4426950408889634f);
    float f = fmaf(n, -0.693145751953125f, t);      // ln2_hi (exact product)
    f = fmaf(n, -1.4286067653e-06f, f);             // ln2_lo
    float p = 1.9841270e-04f;                        // 1/5040
    p = fmaf(p, f, 1.3888889e-03f);                  // 1/720
    p = fmaf(p, f, 8.3333333e-03f);                  // 1/120
    p = fmaf(p, f, 4.1666668e-02f);                  // 1/24
    p = fmaf(p, f, 1.6666667e-01f);                  // 1/6
    p = fmaf(p, f, 0.5f);
    p = fmaf(p, f, 1.0f);
    p = fmaf(p, f, 1.0f);
    int ni = (int)n;                                 // |n| <= 126
    float sc = __int_as_float((ni + 127) << 23);
    return p * sc;
}
__device__ __forceinline__ float sig_p(float x) {
    float e = exp_p(-x);
    return __fdiv_rn(1.0f, 1.0f + e);                // correctly-rounded div
}
__device__ __forceinline__ float tanh_p(float x) {
    float a = fabsf(x);
    float e = exp_p(-2.0f * a);
    float r = __fdiv_rn(1.0f - e, 1.0f + e);
    return copysignf(r, x);
}

// ---------------- weight rearrangement ----------------
__global__ void prep_kernel(const float* __restrict__ W0f, const float* __restrict__ U0f,
                            const float* __restrict__ b0f, const float* __restrict__ W0b,
                            const float* __restrict__ U0b, const float* __restrict__ b0b,
                            const float* __restrict__ Wf, const float* __restrict__ Uf,
                            const float* __restrict__ bf, const float* __restrict__ Wb,
                            const float* __restrict__ Ub, const float* __restrict__ bb) {
    int idx0 = blockIdx.x * blockDim.x + threadIdx.x;
    int stride = gridDim.x * blockDim.x;
    // Ure: 3*2*256*1024
    for (int i = idx0; i < 3 * 2 * 256 * 1024; i += stride) {
        int j = i & 1023;
        int k = (i >> 10) & 255;
        int d = (i >> 18) & 1;
        int l = i >> 19;
        int u = j >> 2, g = j & 3;
        const float* Us = (l == 0) ? (d ? U0b : U0f)
                                   : (d ? Ub + (size_t)(l - 1) * 256 * 1024
                                        : Uf + (size_t)(l - 1) * 256 * 1024);
        g_Ure[l][d][k * 1024 + j] = Us[k * 1024 + g * 256 + u];
    }
    // Wcat: 2*512*2048
    for (int i = idx0; i < 2 * 512 * 2048; i += stride) {
        int j2 = i & 2047;
        int k = (i >> 11) & 511;
        int l = i >> 20;
        int d = j2 >> 10;
        int j = j2 & 1023;
        int u = j >> 2, g = j & 3;
        const float* Ws = d ? Wb : Wf;
        g_Wcat[l][k * 2048 + j2] = Ws[(size_t)l * 512 * 1024 + k * 1024 + g * 256 + u];
    }
    // bcat: 2*2048
    for (int i = idx0; i < 2 * 2048; i += stride) {
        int j2 = i & 2047;
        int l = i >> 11;
        int d = j2 >> 10;
        int j = j2 & 1023;
        int u = j >> 2, g = j & 3;
        const float* bs = d ? bb : bf;
        g_bcat[l][j2] = bs[l * 1024 + g * 256 + u];
    }
    // layer0 W0, b0
    for (int i = idx0; i < 2 * 1024; i += stride) {
        int j = i & 1023;
        int d = i >> 10;
        int u = j >> 2, g = j & 3;
        g_W0re[d][j] = (d ? W0b : W0f)[g * 256 + u];
        g_b0re[d][j] = (d ? b0b : b0f)[g * 256 + u];
    }
}

// ---------------- per-layer init ----------------
__global__ void pre_recur_kernel(int zero_init) {
    int idx = blockIdx.x * blockDim.x + threadIdx.x;
    int stride = gridDim.x * blockDim.x;
    if (idx < 2) g_cnt[idx] = 0;
    float* hb = &g_hbuf[0][0][0];
    const float* sh = &g_stateH[0][0];
    float* sc = &g_stateC[0][0];
    for (int i = idx; i < 2 * UU * NB; i += stride) {
        hb[i] = zero_init ? 0.0f : sh[i];
        if (zero_init) sc[i] = 0.0f;
    }
}

// ---------------- recurrent kernel ----------------
// 128 CTAs (64 per direction), 128 threads; warp = unit, lane = batch.
// Per-step grid barrier: release-RMW on publish, acquire-load spin on wait.
__global__ void __launch_bounds__(128, 1)
recur_kernel(const float* __restrict__ x0, float* __restrict__ dout,
             int layer, int is_last, int wstates) {
    __shared__ __align__(16) float h_s[UU * NB];   // 32 KB  [k][b]
    __shared__ __align__(16) float U_s[UU * 16];   // 16 KB  [k][16]

    const int cta = blockIdx.x;
    const int dir = cta >> 6;
    const int uq = cta & 63;
    const int tid = threadIdx.x;
    const int w = tid >> 5;
    const int b = tid & 31;
    const int u = uq * 4 + w;

    {
        const float* Up = g_Ure[layer][dir];
        for (int i = tid; i < 1024; i += 128) {
            int k = i >> 2, q = i & 3;
            *(float4*)&U_s[k * 16 + q * 4] =
                *(const float4*)&Up[(size_t)k * 1024 + uq * 16 + q * 4];
        }
    }
    float4 w0v = make_float4(0.f, 0.f, 0.f, 0.f), b0v = w0v;
    if (layer == 0) {
        w0v = *(const float4*)&g_W0re[dir][u * 4];
        b0v = *(const float4*)&g_b0re[dir][u * 4];
    }
    float c = g_stateC[dir][u * 32 + b];

    float* xout = is_last ? dout : (layer == 0 ? g_X1 : g_X2);
    unsigned* cntp = &g_cnt[dir];
    const float* xzbase = g_xz + dir * 1024 + uq * 16 + w * 4;

    __syncthreads();

    for (int s = 0; s < TT; ++s) {
        const int t = dir ? (TT - 1 - s) : s;

        // prefetch input gate preacts
        float4 xzv;
        if (layer == 0) {
            float xv = __ldg(&x0[(size_t)b * TT + t]);
            xzv.x = fmaf(xv, w0v.x, b0v.x);
            xzv.y = fmaf(xv, w0v.y, b0v.y);
            xzv.z = fmaf(xv, w0v.z, b0v.z);
            xzv.w = fmaf(xv, w0v.w, b0v.w);
        } else {
            xzv = __ldg((const float4*)(xzbase + ((size_t)t * NB + b) * 2048));
        }

        // wait for previous step (acquire)
        if (s > 0) {
            if (tid == 0) {
                const unsigned target = (unsigned)(64 * s);
                unsigned v;
                do {
                    asm volatile("ld.acquire.gpu.global.u32 %0, [%1];"
                                 : "=r"(v) : "l"(cntp) : "memory");
                } while (v < target);
            }
            __syncthreads();
        }

        // broadcast h into smem (L1-bypass reads of double-buffered global)
        {
            const float* hb = &g_hbuf[s & 1][dir][0];
            for (int i = tid * 4; i < UU * NB; i += 512) {
                float4 hv = __ldcg((const float4*)(hb + i));
                *(float4*)&h_s[i] = hv;
            }
        }
        __syncthreads();

        // z = xz + h @ U  (4 gates of unit u, batch b)
        unsigned long long aif = pack2b(xzv.x, xzv.y);
        unsigned long long ago = pack2b(xzv.z, xzv.w);
#pragma unroll 8
        for (int k = 0; k < UU; ++k) {
            float hk = h_s[k * 32 + b];
            float4 uv = *(const float4*)&U_s[k * 16 + w * 4];
            unsigned long long h2 = pack2(hk);
            fma2(aif, h2, pack2b(uv.x, uv.y));
            fma2(ago, h2, pack2b(uv.z, uv.w));
        }
        float2 f_if = unpack2(aif);
        float2 f_go = unpack2(ago);
        float zi = f_if.x, zf = f_if.y, zg = f_go.x, zo = f_go.y;

        c = sig_p(zf) * c + sig_p(zi) * tanh_p(zg);
        float h = sig_p(zo) * tanh_p(c);

        // publish h for next step
        g_hbuf[(s + 1) & 1][dir][u * 32 + b] = h;
        // layer output
        if (is_last)
            xout[((size_t)b * TT + t) * 512 + dir * 256 + u] = h;
        else
            xout[((size_t)t * NB + b) * 512 + dir * 256 + u] = h;

        if (s == TT - 1) {
            g_stateH[dir][u * 32 + b] = h;
            g_stateC[dir][u * 32 + b] = c;
            if (is_last && wstates) {
                float* tail = dout + OUT_MAIN + (size_t)dir * 2 * NB * UU;
                tail[b * UU + u] = h;
                tail[NB * UU + b * UU + u] = c;
            }
        }

        __syncthreads();
        if (tid == 0) {
            asm volatile("red.release.gpu.global.add.u32 [%0], %1;"
                         :: "l"(cntp), "r"(1u) : "memory");
        }
    }
}

// ---------------- projection GEMM: C[65536,2048] = A[65536,512] @ W[512,2048] + bias ----
#define BM 64
#define BN 64
#define BK 32
__global__ void __launch_bounds__(128)
gemm_kernel(int l) {
    __shared__ __align__(16) float As[BK * BM];  // [k][m]
    __shared__ __align__(16) float Ws[BK * BN];  // [k][n]

    const float* A = (l == 0) ? g_X1 : g_X2;
    const float* W = g_Wcat[l];
    const float* bias = g_bcat[l];
    float* C = g_xz;

    const int r0 = blockIdx.x * BM;
    const int n0 = blockIdx.y * BN;
    const int tid = threadIdx.x;
    const int tr = tid >> 3;
    const int tc = tid & 7;

    unsigned long long acc[4][4];
#pragma unroll
    for (int i = 0; i < 4; ++i)
#pragma unroll
        for (int j = 0; j < 4; ++j) acc[i][j] = pack2b(0.f, 0.f);

    for (int kk = 0; kk < 512; kk += BK) {
#pragma unroll
        for (int it = 0; it < 4; ++it) {
            int idx = tid + it * 128;
            int m = idx >> 3, q = idx & 7;
            float4 av = *(const float4*)&A[(size_t)(r0 + m) * 512 + kk + q * 4];
            As[(q * 4 + 0) * BM + m] = av.x;
            As[(q * 4 + 1) * BM + m] = av.y;
            As[(q * 4 + 2) * BM + m] = av.z;
            As[(q * 4 + 3) * BM + m] = av.w;
        }
#pragma unroll
        for (int it = 0; it < 4; ++it) {
            int idx = tid + it * 128;
            int k = idx >> 4, q = idx & 15;
            *(float4*)&Ws[k * BN + q * 4] =
                *(const float4*)&W[(size_t)(kk + k) * 2048 + n0 + q * 4];
        }
        __syncthreads();

#pragma unroll
        for (int k = 0; k < BK; ++k) {
            float4 av = *(const float4*)&As[k * BM + tr * 4];
            float4 wv0 = *(const float4*)&Ws[k * BN + tc * 8];
            float4 wv1 = *(const float4*)&Ws[k * BN + tc * 8 + 4];
            unsigned long long wp0 = pack2b(wv0.x, wv0.y);
            unsigned long long wp1 = pack2b(wv0.z, wv0.w);
            unsigned long long wp2 = pack2b(wv1.x, wv1.y);
            unsigned long long wp3 = pack2b(wv1.z, wv1.w);
            float am[4] = {av.x, av.y, av.z, av.w};
#pragma unroll
            for (int i = 0; i < 4; ++i) {
                unsigned long long a2 = pack2(am[i]);
                fma2(acc[i][0], a2, wp0);
                fma2(acc[i][1], a2, wp1);
                fma2(acc[i][2], a2, wp2);
                fma2(acc[i][3], a2, wp3);
            }
        }
        __syncthreads();
    }

    float4 bv0 = *(const float4*)&bias[n0 + tc * 8];
    float4 bv1 = *(const float4*)&bias[n0 + tc * 8 + 4];
#pragma unroll
    for (int i = 0; i < 4; ++i) {
        int row = r0 + tr * 4 + i;
        float2 p0 = unpack2(acc[i][0]);
        float2 p1 = unpack2(acc[i][1]);
        float2 p2 = unpack2(acc[i][2]);
        float2 p3 = unpack2(acc[i][3]);
        float4 o0 = make_float4(p0.x + bv0.x, p0.y + bv0.y, p1.x + bv0.z, p1.y + bv0.w);
        float4 o1 = make_float4(p2.x + bv1.x, p2.y + bv1.y, p3.x + bv1.z, p3.y + bv1.w);
        *(float4*)&C[(size_t)row * 2048 + n0 + tc * 8] = o0;
        *(float4*)&C[(size_t)row * 2048 + n0 + tc * 8 + 4] = o1;
    }
}

// ---------------- launch ----------------
extern "C" void kernel_launch(void* const* d_in, const int* in_sizes, int n_in,
                              void* d_out, int out_size) {
    const float* inputs = (const float*)d_in[0];
    const float* W0f = (const float*)d_in[1];
    const float* U0f = (const float*)d_in[2];
    const float* b0f = (const float*)d_in[3];
    const float* W0b = (const float*)d_in[4];
    const float* U0b = (const float*)d_in[5];
    const float* b0b = (const float*)d_in[6];
    const float* Wf = (const float*)d_in[7];
    const float* Uf = (const float*)d_in[8];
    const float* bf = (const float*)d_in[9];
    const float* Wb = (const float*)d_in[10];
    const float* Ub = (const float*)d_in[11];
    const float* bb = (const float*)d_in[12];
    float* out = (float*)d_out;

    int wstates = ((size_t)out_size >= OUT_FULL) ? 1 : 0;

    prep_kernel<<<512, 256>>>(W0f, U0f, b0f, W0b, U0b, b0b, Wf, Uf, bf, Wb, Ub, bb);

    // layer 0
    pre_recur_kernel<<<64, 256>>>(1);
    recur_kernel<<<128, 128>>>(inputs, out, 0, 0, 0);

    // layer 1
    gemm_kernel<<<dim3(TT * NB / BM, 2048 / BN), 128>>>(0);
    pre_recur_kernel<<<64, 256>>>(0);
    recur_kernel<<<128, 128>>>(nullptr, out, 1, 0, 0);

    // layer 2
    gemm_kernel<<<dim3(TT * NB / BM, 2048 / BN), 128>>>(1);
    pre_recur_kernel<<<64, 256>>>(0);
    recur_kernel<<<128, 128>>>(nullptr, out, 2, 1, wstates);
}

// round 5
// speedup vs baseline: 1.1567x; 1.1567x over previous
#include <cuda_runtime.h>
#include <cuda_bf16.h>
#include <cstdint>
#include <cstddef>

// Problem dims
#define TT 2048
#define NB 32
#define UU 256
#define OUT_MAIN ((size_t)NB * TT * 512)
#define OUT_FULL (OUT_MAIN + 4 * (size_t)NB * UU)

// ---------------- static device scratch ----------------
__device__ float g_xz[(size_t)TT * NB * 2048];   // [t*32+b][2048] gate preacts
__device__ float g_X1[(size_t)TT * NB * 512];    // layer0 output [t][b][512]
__device__ float g_X2[(size_t)TT * NB * 512];    // layer1 output
__device__ float g_Ure[3][2][UU * 1024];         // [layer][dir][k][u*4+g]
__device__ float g_Wcat[2][512 * 2048];          // [l][k][d*1024 + u*4+g]
__device__ float g_bcat[2][2048];
__device__ float g_W0re[2][1024];
__device__ float g_b0re[2][1024];
__device__ float g_hbuf[2][2][UU * NB];          // [phase][dir][u*32+b]
__device__ float g_stateH[2][UU * NB];
__device__ float g_stateC[2][UU * NB];
__device__ unsigned g_cnt[2];

// ---------------- packed f32x2 helpers ----------------
__device__ __forceinline__ void fma2(unsigned long long& d, unsigned long long a,
                                     unsigned long long b) {
    asm("fma.rn.f32x2 %0, %1, %2, %0;" : "+l"(d) : "l"(a), "l"(b));
}
__device__ __forceinline__ void add2(unsigned long long& d, unsigned long long a) {
    asm("add.rn.f32x2 %0, %0, %1;" : "+l"(d) : "l"(a));
}
__device__ __forceinline__ unsigned long long pack2b(float x, float y) {
    unsigned long long r;
    asm("mov.b64 %0, {%1, %2};" : "=l"(r) : "f"(x), "f"(y));
    return r;
}
__device__ __forceinline__ float2 unpack2(unsigned long long v) {
    float2 f;
    asm("mov.b64 {%0, %1}, %2;" : "=f"(f.x), "=f"(f.y) : "l"(v));
    return f;
}

// ---------------- fast-math-immune activations ----------------
__device__ __forceinline__ float exp_p(float x) {
    float t = fminf(fmaxf(x, -87.0f), 87.0f);
    float n = rintf(t * 1.4426950408889634f);
    float f = fmaf(n, -0.693145751953125f, t);
    f = fmaf(n, -1.4286067653e-06f, f);
    float p = 1.9841270e-04f;
    p = fmaf(p, f, 1.3888889e-03f);
    p = fmaf(p, f, 8.3333333e-03f);
    p = fmaf(p, f, 4.1666668e-02f);
    p = fmaf(p, f, 1.6666667e-01f);
    p = fmaf(p, f, 0.5f);
    p = fmaf(p, f, 1.0f);
    p = fmaf(p, f, 1.0f);
    int ni = (int)n;
    float sc = __int_as_float((ni + 127) << 23);
    return p * sc;
}
__device__ __forceinline__ float rcp_nr(float d) {
    float r;
    asm("rcp.approx.f32 %0, %1;" : "=f"(r) : "f"(d));
    r = fmaf(r, fmaf(-d, r, 1.0f), r);   // one Newton step -> ~2^-22
    return r;
}
__device__ __forceinline__ float sig_p(float x) {
    return rcp_nr(1.0f + exp_p(-x));
}
__device__ __forceinline__ float tanh_p(float x) {
    float a = fabsf(x);
    float e = exp_p(-2.0f * a);
    float r = (1.0f - e) * rcp_nr(1.0f + e);
    return copysignf(r, x);
}

// ---------------- weight rearrangement ----------------
__global__ void prep_kernel(const float* __restrict__ W0f, const float* __restrict__ U0f,
                            const float* __restrict__ b0f, const float* __restrict__ W0b,
                            const float* __restrict__ U0b, const float* __restrict__ b0b,
                            const float* __restrict__ Wf, const float* __restrict__ Uf,
                            const float* __restrict__ bf, const float* __restrict__ Wb,
                            const float* __restrict__ Ub, const float* __restrict__ bb) {
    int idx0 = blockIdx.x * blockDim.x + threadIdx.x;
    int stride = gridDim.x * blockDim.x;
    for (int i = idx0; i < 3 * 2 * 256 * 1024; i += stride) {
        int j = i & 1023;
        int k = (i >> 10) & 255;
        int d = (i >> 18) & 1;
        int l = i >> 19;
        int u = j >> 2, g = j & 3;
        const float* Us = (l == 0) ? (d ? U0b : U0f)
                                   : (d ? Ub + (size_t)(l - 1) * 256 * 1024
                                        : Uf + (size_t)(l - 1) * 256 * 1024);
        g_Ure[l][d][k * 1024 + j] = Us[k * 1024 + g * 256 + u];
    }
    for (int i = idx0; i < 2 * 512 * 2048; i += stride) {
        int j2 = i & 2047;
        int k = (i >> 11) & 511;
        int l = i >> 20;
        int d = j2 >> 10;
        int j = j2 & 1023;
        int u = j >> 2, g = j & 3;
        const float* Ws = d ? Wb : Wf;
        g_Wcat[l][k * 2048 + j2] = Ws[(size_t)l * 512 * 1024 + k * 1024 + g * 256 + u];
    }
    for (int i = idx0; i < 2 * 2048; i += stride) {
        int j2 = i & 2047;
        int l = i >> 11;
        int d = j2 >> 10;
        int j = j2 & 1023;
        int u = j >> 2, g = j & 3;
        const float* bs = d ? bb : bf;
        g_bcat[l][j2] = bs[l * 1024 + g * 256 + u];
    }
    for (int i = idx0; i < 2 * 1024; i += stride) {
        int j = i & 1023;
        int d = i >> 10;
        int u = j >> 2, g = j & 3;
        g_W0re[d][j] = (d ? W0b : W0f)[g * 256 + u];
        g_b0re[d][j] = (d ? b0b : b0f)[g * 256 + u];
    }
}

// ---------------- per-layer init ----------------
__global__ void pre_recur_kernel(int zero_init) {
    int idx = blockIdx.x * blockDim.x + threadIdx.x;
    int stride = gridDim.x * blockDim.x;
    if (idx < 2) g_cnt[idx] = 0;
    float* hb = &g_hbuf[0][0][0];
    const float* sh = &g_stateH[0][0];
    float* sc = &g_stateC[0][0];
    for (int i = idx; i < 2 * UU * NB; i += stride) {
        hb[i] = zero_init ? 0.0f : sh[i];
        if (zero_init) sc[i] = 0.0f;
    }
}

// ---------------- recurrent kernel ----------------
// 128 CTAs (64/dir) x 256 threads. 8 warps: warp = (khalf<<2)|unit, lane = batch.
// Dup-h smem: inner loop = LDS.64 + LDS.128 + 2x FFMA2 per k (FMA-pipe bound).
__global__ void __launch_bounds__(256, 1)
recur_kernel(const float* __restrict__ x0, float* __restrict__ dout,
             int layer, int is_last, int wstates) {
    extern __shared__ __align__(16) unsigned char smraw[];
    float* h_dup = (float*)smraw;                                        // [256][64] 64KB
    unsigned long long* U2s = (unsigned long long*)(smraw + 65536);      // [256][8]  16KB
    unsigned long long* red_s = (unsigned long long*)(smraw + 65536 + 16384); // 2KB

    const int cta = blockIdx.x;
    const int dir = cta >> 6;
    const int uq = cta & 63;
    const int tid = threadIdx.x;
    const int w = tid >> 5;
    const int b = tid & 31;
    const int kh = w >> 2;
    const int uw = w & 3;
    const int u = uq * 4 + uw;

    // stage U slice: [k][unit] float4 (i,f,g,o) -> 2 ull (if),(go)
    {
        const float* Up = g_Ure[layer][dir];
        for (int i = tid; i < 1024; i += 256) {
            int k = i >> 2, q = i & 3;
            float4 v = *(const float4*)&Up[(size_t)k * 1024 + (uq * 4 + q) * 4];
            *(float4*)&U2s[k * 8 + q * 2] = v;
        }
    }
    float4 w0v = make_float4(0.f, 0.f, 0.f, 0.f), b0v = w0v;
    if (layer == 0) {
        w0v = *(const float4*)&g_W0re[dir][u * 4];
        b0v = *(const float4*)&g_b0re[dir][u * 4];
    }
    float c = g_stateC[dir][u * 32 + b];

    float* xout = is_last ? dout : (layer == 0 ? g_X1 : g_X2);
    unsigned* cntp = &g_cnt[dir];
    const float* xzbase = g_xz + dir * 1024 + uq * 16 + uw * 4;

    __syncthreads();

    for (int s = 0; s < TT; ++s) {
        const int t = dir ? (TT - 1 - s) : s;

        float4 xzv = make_float4(0.f, 0.f, 0.f, 0.f);
        if (kh == 0) {
            if (layer == 0) {
                float xv = __ldg(&x0[(size_t)b * TT + t]);
                xzv.x = fmaf(xv, w0v.x, b0v.x);
                xzv.y = fmaf(xv, w0v.y, b0v.y);
                xzv.z = fmaf(xv, w0v.z, b0v.z);
                xzv.w = fmaf(xv, w0v.w, b0v.w);
            } else {
                xzv = __ldg((const float4*)(xzbase + ((size_t)t * NB + b) * 2048));
            }
        }

        if (s > 0 && tid == 0) {
            const unsigned target = (unsigned)(64 * s);
            unsigned v;
            do {
                asm volatile("ld.acquire.gpu.global.u32 %0, [%1];"
                             : "=r"(v) : "l"(cntp) : "memory");
            } while (v < target);
        }
        __syncthreads();

        // stage h (dup pairs) into smem
        {
            const float4* hb4 = (const float4*)&g_hbuf[s & 1][dir][0];
#pragma unroll
            for (int r = 0; r < 8; ++r) {
                int i = tid + r * 256;             // float4 idx 0..2047
                float4 v = __ldcg(hb4 + i);
                int k = i >> 3;
                int b8 = (i & 7) << 3;
                float* dst = &h_dup[k * 64 + b8];
                *(float4*)dst = make_float4(v.x, v.x, v.y, v.y);
                *(float4*)(dst + 4) = make_float4(v.z, v.z, v.w, v.w);
            }
        }
        __syncthreads();

        unsigned long long aif, ago;
        if (kh == 0) { aif = pack2b(xzv.x, xzv.y); ago = pack2b(xzv.z, xzv.w); }
        else         { aif = 0ULL; ago = 0ULL; }

        const float* hp = &h_dup[kh * 128 * 64 + 2 * b];
        const unsigned long long* up = &U2s[kh * 128 * 8 + uw * 2];
#pragma unroll 8
        for (int k = 0; k < 128; ++k) {
            unsigned long long h2 = *(const unsigned long long*)(hp + (size_t)k * 64);
            ulonglong2 uv = *(const ulonglong2*)(up + (size_t)k * 8);
            fma2(aif, h2, uv.x);
            fma2(ago, h2, uv.y);
        }
        if (kh == 1) {
            ulonglong2 pv;
            pv.x = aif; pv.y = ago;
            *(ulonglong2*)&red_s[(uw * 32 + b) * 2] = pv;
        }
        __syncthreads();

        if (kh == 0) {
            ulonglong2 pv = *(const ulonglong2*)&red_s[(uw * 32 + b) * 2];
            add2(aif, pv.x);
            add2(ago, pv.y);
            float2 fif = unpack2(aif), fgo = unpack2(ago);
            float zi = fif.x, zf = fif.y, zg = fgo.x, zo = fgo.y;

            c = sig_p(zf) * c + sig_p(zi) * tanh_p(zg);
            float h = sig_p(zo) * tanh_p(c);

            // publish h ASAP, then release
            g_hbuf[(s + 1) & 1][dir][u * 32 + b] = h;
            asm volatile("bar.sync 1, 128;" ::: "memory");
            if (tid == 0) {
                asm volatile("red.release.gpu.global.add.u32 [%0], %1;"
                             :: "l"(cntp), "r"(1u) : "memory");
            }

            if (is_last)
                dout[((size_t)b * TT + t) * 512 + dir * 256 + u] = h;
            else
                xout[((size_t)t * NB + b) * 512 + dir * 256 + u] = h;

            if (s == TT - 1) {
                g_stateH[dir][u * 32 + b] = h;
                g_stateC[dir][u * 32 + b] = c;
                if (is_last && wstates) {
                    float* tail = dout + OUT_MAIN + (size_t)dir * 2 * NB * UU;
                    tail[b * UU + u] = h;
                    tail[NB * UU + b * UU + u] = c;
                }
            }
        }
    }
}

// ---------------- projection GEMM: C[65536,2048] = A[65536,512] @ W[512,2048] + bias ----
#define GBM 128
#define GBN 128
#define GBK 16
#define AS_LD 264                 // floats per k-row of dup-A (2*128 + 8 pad)
#define AS_BUF (GBK * AS_LD)      // 4224 floats
#define WS_BUF (GBK * GBN)        // 2048 floats
#define GEMM_SMEM ((2 * AS_BUF + 2 * WS_BUF) * 4)

__global__ void __launch_bounds__(256)
gemm_kernel(int l) {
    extern __shared__ __align__(16) float gsm[];
    float* As = gsm;
    float* Ws = gsm + 2 * AS_BUF;

    const float* A = (l == 0) ? g_X1 : g_X2;
    const float* W = g_Wcat[l];
    const float* bias = g_bcat[l];
    float* C = g_xz;

    const int r0 = blockIdx.x * GBM;
    const int n0 = blockIdx.y * GBN;
    const int tid = threadIdx.x;
    const int tx = tid & 15;
    const int ty = tid >> 4;

    const int arow = tid >> 2;     // 0..63
    const int akq = tid & 3;       // k float4 idx
    const int wk = tid >> 5;       // 0..7
    const int wn = tid & 31;       // n float4 idx

    unsigned long long acc[8][4];
#pragma unroll
    for (int i = 0; i < 8; ++i)
#pragma unroll
        for (int j = 0; j < 4; ++j) acc[i][j] = 0ULL;

    const float* Ag = A + (size_t)(r0 + arow) * 512 + akq * 4;
    const float* Wg = W + (size_t)wk * 2048 + n0 + wn * 4;

    float4 ra0 = __ldg((const float4*)Ag);
    float4 ra1 = __ldg((const float4*)(Ag + (size_t)64 * 512));
    float4 rw0 = __ldg((const float4*)Wg);
    float4 rw1 = __ldg((const float4*)(Wg + (size_t)8 * 2048));

    for (int kt = 0; kt < 32; ++kt) {
        const int buf = kt & 1;
        float* as = As + buf * AS_BUF;
        float* ws = Ws + buf * WS_BUF;

        // A: transpose + duplicate
        {
            float* d0 = as + (akq * 4 + 0) * AS_LD;
            float* d1 = as + (akq * 4 + 1) * AS_LD;
            float* d2 = as + (akq * 4 + 2) * AS_LD;
            float* d3 = as + (akq * 4 + 3) * AS_LD;
            int m0 = 2 * arow, m1 = 2 * (arow + 64);
            d0[m0] = ra0.x; d0[m0 + 1] = ra0.x; d0[m1] = ra1.x; d0[m1 + 1] = ra1.x;
            d1[m0] = ra0.y; d1[m0 + 1] = ra0.y; d1[m1] = ra1.y; d1[m1 + 1] = ra1.y;
            d2[m0] = ra0.z; d2[m0 + 1] = ra0.z; d2[m1] = ra1.z; d2[m1 + 1] = ra1.z;
            d3[m0] = ra0.w; d3[m0 + 1] = ra0.w; d3[m1] = ra1.w; d3[m1 + 1] = ra1.w;
        }
        *(float4*)&ws[wk * GBN + wn * 4] = rw0;
        *(float4*)&ws[(wk + 8) * GBN + wn * 4] = rw1;
        __syncthreads();

        if (kt < 31) {
            ra0 = __ldg((const float4*)(Ag + (kt + 1) * 16));
            ra1 = __ldg((const float4*)(Ag + (size_t)64 * 512 + (kt + 1) * 16));
            rw0 = __ldg((const float4*)(Wg + (size_t)(kt + 1) * 16 * 2048));
            rw1 = __ldg((const float4*)(Wg + (size_t)(kt + 1) * 16 * 2048 + (size_t)8 * 2048));
        }

#pragma unroll
        for (int k = 0; k < GBK; ++k) {
            const float* ar = as + k * AS_LD + ty * 16;
            ulonglong2 a01 = *(const ulonglong2*)(ar);
            ulonglong2 a23 = *(const ulonglong2*)(ar + 4);
            ulonglong2 a45 = *(const ulonglong2*)(ar + 8);
            ulonglong2 a67 = *(const ulonglong2*)(ar + 12);
            const unsigned long long* wr =
                (const unsigned long long*)(ws + k * GBN + tx * 8);
            ulonglong2 w01 = *(const ulonglong2*)(wr);
            ulonglong2 w23 = *(const ulonglong2*)(wr + 2);

            unsigned long long am[8] = {a01.x, a01.y, a23.x, a23.y,
                                        a45.x, a45.y, a67.x, a67.y};
            unsigned long long wp[4] = {w01.x, w01.y, w23.x, w23.y};
#pragma unroll
            for (int m = 0; m < 8; ++m)
#pragma unroll
                for (int j = 0; j < 4; ++j) fma2(acc[m][j], am[m], wp[j]);
        }
        __syncthreads();
    }

    float4 bv0 = *(const float4*)&bias[n0 + tx * 8];
    float4 bv1 = *(const float4*)&bias[n0 + tx * 8 + 4];
#pragma unroll
    for (int m = 0; m < 8; ++m) {
        int row = r0 + ty * 8 + m;
        float2 p0 = unpack2(acc[m][0]);
        float2 p1 = unpack2(acc[m][1]);
        float2 p2 = unpack2(acc[m][2]);
        float2 p3 = unpack2(acc[m][3]);
        float4 o0 = make_float4(p0.x + bv0.x, p0.y + bv0.y, p1.x + bv0.z, p1.y + bv0.w);
        float4 o1 = make_float4(p2.x + bv1.x, p2.y + bv1.y, p3.x + bv1.z, p3.y + bv1.w);
        float* cp = &C[(size_t)row * 2048 + n0 + tx * 8];
        *(float4*)cp = o0;
        *(float4*)(cp + 4) = o1;
    }
}

// ---------------- launch ----------------
#define RECUR_SMEM (65536 + 16384 + 2048)

extern "C" void kernel_launch(void* const* d_in, const int* in_sizes, int n_in,
                              void* d_out, int out_size) {
    const float* inputs = (const float*)d_in[0];
    const float* W0f = (const float*)d_in[1];
    const float* U0f = (const float*)d_in[2];
    const float* b0f = (const float*)d_in[3];
    const float* W0b = (const float*)d_in[4];
    const float* U0b = (const float*)d_in[5];
    const float* b0b = (const float*)d_in[6];
    const float* Wf = (const float*)d_in[7];
    const float* Uf = (const float*)d_in[8];
    const float* bf = (const float*)d_in[9];
    const float* Wb = (const float*)d_in[10];
    const float* Ub = (const float*)d_in[11];
    const float* bb = (const float*)d_in[12];
    float* out = (float*)d_out;

    int wstates = ((size_t)out_size >= OUT_FULL) ? 1 : 0;

    cudaFuncSetAttribute(recur_kernel, cudaFuncAttributeMaxDynamicSharedMemorySize,
                         RECUR_SMEM);
    cudaFuncSetAttribute(gemm_kernel, cudaFuncAttributeMaxDynamicSharedMemorySize,
                         GEMM_SMEM);

    prep_kernel<<<512, 256>>>(W0f, U0f, b0f, W0b, U0b, b0b, Wf, Uf, bf, Wb, Ub, bb);

    // layer 0
    pre_recur_kernel<<<64, 256>>>(1);
    recur_kernel<<<128, 256, RECUR_SMEM>>>(inputs, out, 0, 0, 0);

    // layer 1
    gemm_kernel<<<dim3(512, 16), 256, GEMM_SMEM>>>(0);
    pre_recur_kernel<<<64, 256>>>(0);
    recur_kernel<<<128, 256, RECUR_SMEM>>>(nullptr, out, 1, 0, 0);

    // layer 2
    gemm_kernel<<<dim3(512, 16), 256, GEMM_SMEM>>>(1);
    pre_recur_kernel<<<64, 256>>>(0);
    recur_kernel<<<128, 256, RECUR_SMEM>>>(nullptr, out, 2, 1, wstates);
}

// round 6
// speedup vs baseline: 1.3192x; 1.1405x over previous
#include <cuda_runtime.h>
#include <cuda_bf16.h>
#include <cstdint>
#include <cstddef>

// Problem dims
#define TT 2048
#define NB 32
#define UU 256
#define OUT_MAIN ((size_t)NB * TT * 512)
#define OUT_FULL (OUT_MAIN + 4 * (size_t)NB * UU)

// ---------------- static device scratch ----------------
__device__ float g_xz[(size_t)TT * NB * 2048];   // [t*32+b][2048] gate preacts
__device__ float g_X1[(size_t)TT * NB * 512];    // layer0 output [t][b][512]
__device__ float g_X2[(size_t)TT * NB * 512];    // layer1 output
__device__ float g_Ure[3][2][UU * 1024];         // [layer][dir][k][u*4+g]
__device__ float g_Wcat[2][512 * 2048];          // [l][k][d*1024 + u*4+g]
__device__ float g_bcat[2][2048];
__device__ float g_W0re[2][1024];
__device__ float g_b0re[2][1024];
__device__ float g_hbuf[2][2][UU * NB];          // [phase][dir][u*32+b]
__device__ float g_stateH[2][UU * NB];
__device__ float g_stateC[2][UU * NB];
__device__ unsigned g_cnt[2];

// ---------------- packed f32x2 helpers ----------------
__device__ __forceinline__ void fma2(unsigned long long& d, unsigned long long a,
                                     unsigned long long b) {
    asm("fma.rn.f32x2 %0, %1, %2, %0;" : "+l"(d) : "l"(a), "l"(b));
}
__device__ __forceinline__ void add2(unsigned long long& d, unsigned long long a) {
    asm("add.rn.f32x2 %0, %0, %1;" : "+l"(d) : "l"(a));
}
__device__ __forceinline__ unsigned long long pack2b(float x, float y) {
    unsigned long long r;
    asm("mov.b64 %0, {%1, %2};" : "=l"(r) : "f"(x), "f"(y));
    return r;
}
__device__ __forceinline__ float2 unpack2(unsigned long long v) {
    float2 f;
    asm("mov.b64 {%0, %1}, %2;" : "=f"(f.x), "=f"(f.y) : "l"(v));
    return f;
}

// ---------------- fast-math-immune activations ----------------
__device__ __forceinline__ float exp_p(float x) {
    float t = fminf(fmaxf(x, -87.0f), 87.0f);
    float n = rintf(t * 1.4426950408889634f);
    float f = fmaf(n, -0.693145751953125f, t);
    f = fmaf(n, -1.4286067653e-06f, f);
    float p = 1.9841270e-04f;
    p = fmaf(p, f, 1.3888889e-03f);
    p = fmaf(p, f, 8.3333333e-03f);
    p = fmaf(p, f, 4.1666668e-02f);
    p = fmaf(p, f, 1.6666667e-01f);
    p = fmaf(p, f, 0.5f);
    p = fmaf(p, f, 1.0f);
    p = fmaf(p, f, 1.0f);
    int ni = (int)n;
    float sc = __int_as_float((ni + 127) << 23);
    return p * sc;
}
__device__ __forceinline__ float rcp_nr(float d) {
    float r;
    asm("rcp.approx.f32 %0, %1;" : "=f"(r) : "f"(d));
    r = fmaf(r, fmaf(-d, r, 1.0f), r);
    return r;
}
__device__ __forceinline__ float sig_p(float x) {
    return rcp_nr(1.0f + exp_p(-x));
}
__device__ __forceinline__ float tanh_p(float x) {
    float a = fabsf(x);
    float e = exp_p(-2.0f * a);
    float r = (1.0f - e) * rcp_nr(1.0f + e);
    return copysignf(r, x);
}

// ---------------- weight rearrangement ----------------
__global__ void prep_kernel(const float* __restrict__ W0f, const float* __restrict__ U0f,
                            const float* __restrict__ b0f, const float* __restrict__ W0b,
                            const float* __restrict__ U0b, const float* __restrict__ b0b,
                            const float* __restrict__ Wf, const float* __restrict__ Uf,
                            const float* __restrict__ bf, const float* __restrict__ Wb,
                            const float* __restrict__ Ub, const float* __restrict__ bb) {
    int idx0 = blockIdx.x * blockDim.x + threadIdx.x;
    int stride = gridDim.x * blockDim.x;
    for (int i = idx0; i < 3 * 2 * 256 * 1024; i += stride) {
        int j = i & 1023;
        int k = (i >> 10) & 255;
        int d = (i >> 18) & 1;
        int l = i >> 19;
        int u = j >> 2, g = j & 3;
        const float* Us = (l == 0) ? (d ? U0b : U0f)
                                   : (d ? Ub + (size_t)(l - 1) * 256 * 1024
                                        : Uf + (size_t)(l - 1) * 256 * 1024);
        g_Ure[l][d][k * 1024 + j] = Us[k * 1024 + g * 256 + u];
    }
    for (int i = idx0; i < 2 * 512 * 2048; i += stride) {
        int j2 = i & 2047;
        int k = (i >> 11) & 511;
        int l = i >> 20;
        int d = j2 >> 10;
        int j = j2 & 1023;
        int u = j >> 2, g = j & 3;
        const float* Ws = d ? Wb : Wf;
        g_Wcat[l][k * 2048 + j2] = Ws[(size_t)l * 512 * 1024 + k * 1024 + g * 256 + u];
    }
    for (int i = idx0; i < 2 * 2048; i += stride) {
        int j2 = i & 2047;
        int l = i >> 11;
        int d = j2 >> 10;
        int j = j2 & 1023;
        int u = j >> 2, g = j & 3;
        const float* bs = d ? bb : bf;
        g_bcat[l][j2] = bs[l * 1024 + g * 256 + u];
    }
    for (int i = idx0; i < 2 * 1024; i += stride) {
        int j = i & 1023;
        int d = i >> 10;
        int u = j >> 2, g = j & 3;
        g_W0re[d][j] = (d ? W0b : W0f)[g * 256 + u];
        g_b0re[d][j] = (d ? b0b : b0f)[g * 256 + u];
    }
}

// ---------------- per-layer init ----------------
__global__ void pre_recur_kernel(int zero_init) {
    int idx = blockIdx.x * blockDim.x + threadIdx.x;
    int stride = gridDim.x * blockDim.x;
    if (idx < 2) g_cnt[idx] = 0;
    float* hb = &g_hbuf[0][0][0];
    const float* sh = &g_stateH[0][0];
    float* sc = &g_stateC[0][0];
    for (int i = idx; i < 2 * UU * NB; i += stride) {
        hb[i] = zero_init ? 0.0f : sh[i];
        if (zero_init) sc[i] = 0.0f;
    }
}

// ---------------- recurrent kernel ----------------
// 128 CTAs (64/dir) x 256 threads. warp = k-chunk (32 k each), lane = batch.
// Each thread accumulates ALL 4 units' gate pairs -> h read once per k per warp.
// Inner loop/k: LDS.64(h dup) + 4x LDS.128 bcast(U) + 8 FFMA2  => FMA-bound.
__global__ void __launch_bounds__(256, 1)
recur_kernel(const float* __restrict__ x0, float* __restrict__ dout,
             int layer, int is_last, int wstates) {
    extern __shared__ __align__(16) unsigned char smraw[];
    float* h_dup = (float*)smraw;                                   // [256][64] 64KB
    unsigned long long* U2s = (unsigned long long*)(smraw + 65536); // [256][8]  16KB
    ulonglong2* red2 = (ulonglong2*)(smraw + 65536 + 16384);        // [8][4][32] 16KB

    const int cta = blockIdx.x;
    const int dir = cta >> 6;
    const int uq = cta & 63;
    const int tid = threadIdx.x;
    const int w = tid >> 5;       // k-chunk
    const int b = tid & 31;       // batch lane

    // stage U slice: per k, 4 units x (if,go) ull pairs
    {
        const float* Up = g_Ure[layer][dir];
        for (int i = tid; i < 1024; i += 256) {
            int k = i >> 2, u = i & 3;
            float4 v = *(const float4*)&Up[(size_t)k * 1024 + (uq * 4 + u) * 4];
            *(float4*)&U2s[k * 8 + u * 2] = v;
        }
    }

    // reducer role: tid < 128 -> (ur, br)
    const int ur = tid >> 5;          // valid when tid < 128
    const int br = tid & 31;
    float4 w0v = make_float4(0.f, 0.f, 0.f, 0.f), b0v = w0v;
    float c = 0.0f;
    if (tid < 128) {
        if (layer == 0) {
            w0v = *(const float4*)&g_W0re[dir][(uq * 4 + ur) * 4];
            b0v = *(const float4*)&g_b0re[dir][(uq * 4 + ur) * 4];
        }
        c = g_stateC[dir][(uq * 4 + ur) * 32 + br];
    }

    float* xout = is_last ? dout : (layer == 0 ? g_X1 : g_X2);
    unsigned* cntp = &g_cnt[dir];
    const float* xzbase = g_xz + dir * 1024 + uq * 16 + ur * 4;

    __syncthreads();

    for (int s = 0; s < TT; ++s) {
        const int t = dir ? (TT - 1 - s) : s;

        // reducers prefetch input preacts (independent of barrier)
        float4 xzv = make_float4(0.f, 0.f, 0.f, 0.f);
        if (tid < 128) {
            if (layer == 0) {
                float xv = __ldg(&x0[(size_t)br * TT + t]);
                xzv.x = fmaf(xv, w0v.x, b0v.x);
                xzv.y = fmaf(xv, w0v.y, b0v.y);
                xzv.z = fmaf(xv, w0v.z, b0v.z);
                xzv.w = fmaf(xv, w0v.w, b0v.w);
            } else {
                xzv = __ldg((const float4*)(xzbase + ((size_t)t * NB + br) * 2048));
            }
        }

        if (s > 0 && tid == 0) {
            const unsigned target = (unsigned)(64 * s);
            unsigned v;
            do {
                asm volatile("ld.acquire.gpu.global.u32 %0, [%1];"
                             : "=r"(v) : "l"(cntp) : "memory");
            } while (v < target);
        }
        __syncthreads();

        // stage h (dup pairs) into smem: h_dup[k][2*bb+{0,1}] = h[k][bb]
        {
            const float4* hb4 = (const float4*)&g_hbuf[s & 1][dir][0];
#pragma unroll
            for (int r = 0; r < 8; ++r) {
                int i = tid + r * 256;            // float4 idx 0..2047
                float4 v = __ldcg(hb4 + i);
                int k = i >> 3;
                int b8 = (i & 7) << 3;
                float* dst = &h_dup[k * 64 + b8];
                *(float4*)dst = make_float4(v.x, v.x, v.y, v.y);
                *(float4*)(dst + 4) = make_float4(v.z, v.z, v.w, v.w);
            }
        }
        __syncthreads();

        // partial gate sums over this warp's 32-k slice, all 4 units
        unsigned long long acc[4][2];
#pragma unroll
        for (int u = 0; u < 4; ++u) { acc[u][0] = 0ULL; acc[u][1] = 0ULL; }
        {
            const float* hp = &h_dup[(w * 32) * 64 + 2 * b];
            const unsigned long long* up = &U2s[(w * 32) * 8];
#pragma unroll 4
            for (int k = 0; k < 32; ++k) {
                unsigned long long h2 = *(const unsigned long long*)(hp + (size_t)k * 64);
                ulonglong2 u0 = *(const ulonglong2*)(up + (size_t)k * 8 + 0);
                ulonglong2 u1 = *(const ulonglong2*)(up + (size_t)k * 8 + 2);
                ulonglong2 u2 = *(const ulonglong2*)(up + (size_t)k * 8 + 4);
                ulonglong2 u3 = *(const ulonglong2*)(up + (size_t)k * 8 + 6);
                fma2(acc[0][0], h2, u0.x); fma2(acc[0][1], h2, u0.y);
                fma2(acc[1][0], h2, u1.x); fma2(acc[1][1], h2, u1.y);
                fma2(acc[2][0], h2, u2.x); fma2(acc[2][1], h2, u2.y);
                fma2(acc[3][0], h2, u3.x); fma2(acc[3][1], h2, u3.y);
            }
        }
#pragma unroll
        for (int u = 0; u < 4; ++u) {
            ulonglong2 pv; pv.x = acc[u][0]; pv.y = acc[u][1];
            red2[(w * 4 + u) * 32 + b] = pv;
        }
        __syncthreads();

        if (tid < 128) {
            unsigned long long aif = pack2b(xzv.x, xzv.y);
            unsigned long long ago = pack2b(xzv.z, xzv.w);
#pragma unroll
            for (int w2 = 0; w2 < 8; ++w2) {
                ulonglong2 pv = red2[(w2 * 4 + ur) * 32 + br];
                add2(aif, pv.x);
                add2(ago, pv.y);
            }
            float2 fif = unpack2(aif), fgo = unpack2(ago);
            float zi = fif.x, zf = fif.y, zg = fgo.x, zo = fgo.y;

            c = sig_p(zf) * c + sig_p(zi) * tanh_p(zg);
            float h = sig_p(zo) * tanh_p(c);

            const int u = uq * 4 + ur;
            g_hbuf[(s + 1) & 1][dir][u * 32 + br] = h;
            asm volatile("bar.sync 1, 128;" ::: "memory");
            if (tid == 0) {
                asm volatile("red.release.gpu.global.add.u32 [%0], %1;"
                             :: "l"(cntp), "r"(1u) : "memory");
            }

            if (is_last)
                dout[((size_t)br * TT + t) * 512 + dir * 256 + u] = h;
            else
                xout[((size_t)t * NB + br) * 512 + dir * 256 + u] = h;

            if (s == TT - 1) {
                g_stateH[dir][u * 32 + br] = h;
                g_stateC[dir][u * 32 + br] = c;
                if (is_last && wstates) {
                    float* tail = dout + OUT_MAIN + (size_t)dir * 2 * NB * UU;
                    tail[br * UU + u] = h;
                    tail[NB * UU + br * UU + u] = c;
                }
            }
        }
    }
}

// ---------------- projection GEMM: C[65536,2048] = A[65536,512] @ W[512,2048] + bias ----
#define GBM 128
#define GBN 128
#define GBK 16
#define AS_LD 264
#define AS_BUF (GBK * AS_LD)
#define WS_BUF (GBK * GBN)
#define GEMM_SMEM ((2 * AS_BUF + 2 * WS_BUF) * 4)

__global__ void __launch_bounds__(256, 2)
gemm_kernel(int l) {
    extern __shared__ __align__(16) float gsm[];
    float* As = gsm;
    float* Ws = gsm + 2 * AS_BUF;

    const float* A = (l == 0) ? g_X1 : g_X2;
    const float* W = g_Wcat[l];
    const float* bias = g_bcat[l];
    float* C = g_xz;

    const int r0 = blockIdx.x * GBM;
    const int n0 = blockIdx.y * GBN;
    const int tid = threadIdx.x;
    const int tx = tid & 15;
    const int ty = tid >> 4;

    const int arow = tid >> 2;
    const int akq = tid & 3;
    const int wk = tid >> 5;
    const int wn = tid & 31;

    unsigned long long acc[8][4];
#pragma unroll
    for (int i = 0; i < 8; ++i)
#pragma unroll
        for (int j = 0; j < 4; ++j) acc[i][j] = 0ULL;

    const float* Ag = A + (size_t)(r0 + arow) * 512 + akq * 4;
    const float* Wg = W + (size_t)wk * 2048 + n0 + wn * 4;

    float4 ra0 = __ldg((const float4*)Ag);
    float4 ra1 = __ldg((const float4*)(Ag + (size_t)64 * 512));
    float4 rw0 = __ldg((const float4*)Wg);
    float4 rw1 = __ldg((const float4*)(Wg + (size_t)8 * 2048));

    for (int kt = 0; kt < 32; ++kt) {
        const int buf = kt & 1;
        float* as = As + buf * AS_BUF;
        float* ws = Ws + buf * WS_BUF;

        {
            float* d0 = as + (akq * 4 + 0) * AS_LD;
            float* d1 = as + (akq * 4 + 1) * AS_LD;
            float* d2 = as + (akq * 4 + 2) * AS_LD;
            float* d3 = as + (akq * 4 + 3) * AS_LD;
            int m0 = 2 * arow, m1 = 2 * (arow + 64);
            d0[m0] = ra0.x; d0[m0 + 1] = ra0.x; d0[m1] = ra1.x; d0[m1 + 1] = ra1.x;
            d1[m0] = ra0.y; d1[m0 + 1] = ra0.y; d1[m1] = ra1.y; d1[m1 + 1] = ra1.y;
            d2[m0] = ra0.z; d2[m0 + 1] = ra0.z; d2[m1] = ra1.z; d2[m1 + 1] = ra1.z;
            d3[m0] = ra0.w; d3[m0 + 1] = ra0.w; d3[m1] = ra1.w; d3[m1 + 1] = ra1.w;
        }
        *(float4*)&ws[wk * GBN + wn * 4] = rw0;
        *(float4*)&ws[(wk + 8) * GBN + wn * 4] = rw1;
        __syncthreads();

        if (kt < 31) {
            ra0 = __ldg((const float4*)(Ag + (kt + 1) * 16));
            ra1 = __ldg((const float4*)(Ag + (size_t)64 * 512 + (kt + 1) * 16));
            rw0 = __ldg((const float4*)(Wg + (size_t)(kt + 1) * 16 * 2048));
            rw1 = __ldg((const float4*)(Wg + (size_t)(kt + 1) * 16 * 2048 + (size_t)8 * 2048));
        }

#pragma unroll
        for (int k = 0; k < GBK; ++k) {
            const float* ar = as + k * AS_LD + ty * 16;
            ulonglong2 a01 = *(const ulonglong2*)(ar);
            ulonglong2 a23 = *(const ulonglong2*)(ar + 4);
            ulonglong2 a45 = *(const ulonglong2*)(ar + 8);
            ulonglong2 a67 = *(const ulonglong2*)(ar + 12);
            const unsigned long long* wr =
                (const unsigned long long*)(ws + k * GBN + tx * 8);
            ulonglong2 w01 = *(const ulonglong2*)(wr);
            ulonglong2 w23 = *(const ulonglong2*)(wr + 2);

            unsigned long long am[8] = {a01.x, a01.y, a23.x, a23.y,
                                        a45.x, a45.y, a67.x, a67.y};
            unsigned long long wp[4] = {w01.x, w01.y, w23.x, w23.y};
#pragma unroll
            for (int m = 0; m < 8; ++m)
#pragma unroll
                for (int j = 0; j < 4; ++j) fma2(acc[m][j], am[m], wp[j]);
        }
        __syncthreads();
    }

    float4 bv0 = *(const float4*)&bias[n0 + tx * 8];
    float4 bv1 = *(const float4*)&bias[n0 + tx * 8 + 4];
#pragma unroll
    for (int m = 0; m < 8; ++m) {
        int row = r0 + ty * 8 + m;
        float2 p0 = unpack2(acc[m][0]);
        float2 p1 = unpack2(acc[m][1]);
        float2 p2 = unpack2(acc[m][2]);
        float2 p3 = unpack2(acc[m][3]);
        float4 o0 = make_float4(p0.x + bv0.x, p0.y + bv0.y, p1.x + bv0.z, p1.y + bv0.w);
        float4 o1 = make_float4(p2.x + bv1.x, p2.y + bv1.y, p3.x + bv1.z, p3.y + bv1.w);
        float* cp = &C[(size_t)row * 2048 + n0 + tx * 8];
        *(float4*)cp = o0;
        *(float4*)(cp + 4) = o1;
    }
}

// ---------------- launch ----------------
#define RECUR_SMEM (65536 + 16384 + 16384)

extern "C" void kernel_launch(void* const* d_in, const int* in_sizes, int n_in,
                              void* d_out, int out_size) {
    const float* inputs = (const float*)d_in[0];
    const float* W0f = (const float*)d_in[1];
    const float* U0f = (const float*)d_in[2];
    const float* b0f = (const float*)d_in[3];
    const float* W0b = (const float*)d_in[4];
    const float* U0b = (const float*)d_in[5];
    const float* b0b = (const float*)d_in[6];
    const float* Wf = (const float*)d_in[7];
    const float* Uf = (const float*)d_in[8];
    const float* bf = (const float*)d_in[9];
    const float* Wb = (const float*)d_in[10];
    const float* Ub = (const float*)d_in[11];
    const float* bb = (const float*)d_in[12];
    float* out = (float*)d_out;

    int wstates = ((size_t)out_size >= OUT_FULL) ? 1 : 0;

    cudaFuncSetAttribute(recur_kernel, cudaFuncAttributeMaxDynamicSharedMemorySize,
                         RECUR_SMEM);
    cudaFuncSetAttribute(gemm_kernel, cudaFuncAttributeMaxDynamicSharedMemorySize,
                         GEMM_SMEM);

    prep_kernel<<<512, 256>>>(W0f, U0f, b0f, W0b, U0b, b0b, Wf, Uf, bf, Wb, Ub, bb);

    // layer 0
    pre_recur_kernel<<<64, 256>>>(1);
    recur_kernel<<<128, 256, RECUR_SMEM>>>(inputs, out, 0, 0, 0);

    // layer 1
    gemm_kernel<<<dim3(512, 16), 256, GEMM_SMEM>>>(0);
    pre_recur_kernel<<<64, 256>>>(0);
    recur_kernel<<<128, 256, RECUR_SMEM>>>(nullptr, out, 1, 0, 0);

    // layer 2
    gemm_kernel<<<dim3(512, 16), 256, GEMM_SMEM>>>(1);
    pre_recur_kernel<<<64, 256>>>(0);
    recur_kernel<<<128, 256, RECUR_SMEM>>>(nullptr, out, 2, 1, wstates);
}

// round 7
// speedup vs baseline: 1.5951x; 1.2092x over previous
#include <cuda_runtime.h>
#include <cuda_bf16.h>
#include <cstdint>
#include <cstddef>

// Problem dims
#define TT 2048
#define NB 32
#define UU 256
#define OUT_MAIN ((size_t)NB * TT * 512)
#define OUT_FULL (OUT_MAIN + 4 * (size_t)NB * UU)

// ---------------- static device scratch ----------------
__device__ float g_xz[(size_t)TT * NB * 2048];   // [t*32+b][2048] gate preacts
__device__ float g_X1[(size_t)TT * NB * 512];    // layer0 output [t][b][512]
__device__ float g_X2[(size_t)TT * NB * 512];    // layer1 output
__device__ float g_Ure[3][2][UU * 1024];         // [layer][dir][k][u*4+g]
__device__ float g_Wcat[2][512 * 2048];          // [l][k][d*1024 + u*4+g]
__device__ float g_bcat[2][2048];
__device__ float g_W0re[2][1024];
__device__ float g_b0re[2][1024];
__device__ float g_hbuf[2][2][UU * NB];          // [phase][dir][k*32+b]
__device__ float g_stateH[2][UU * NB];
__device__ float g_stateC[2][UU * NB];
__device__ unsigned g_cnt[2];

// ---------------- packed f32x2 helpers ----------------
__device__ __forceinline__ void fma2(unsigned long long& d, unsigned long long a,
                                     unsigned long long b) {
    asm("fma.rn.f32x2 %0, %1, %2, %0;" : "+l"(d) : "l"(a), "l"(b));
}
__device__ __forceinline__ void add2(unsigned long long& d, unsigned long long a) {
    asm("add.rn.f32x2 %0, %0, %1;" : "+l"(d) : "l"(a));
}
__device__ __forceinline__ unsigned long long pack2(float x) {
    unsigned long long r;
    asm("mov.b64 %0, {%1, %1};" : "=l"(r) : "f"(x));
    return r;
}
__device__ __forceinline__ unsigned long long pack2b(float x, float y) {
    unsigned long long r;
    asm("mov.b64 %0, {%1, %2};" : "=l"(r) : "f"(x), "f"(y));
    return r;
}
__device__ __forceinline__ float2 unpack2(unsigned long long v) {
    float2 f;
    asm("mov.b64 {%0, %1}, %2;" : "=f"(f.x), "=f"(f.y) : "l"(v));
    return f;
}

// ---------------- fast-math-immune activations ----------------
__device__ __forceinline__ float exp_p(float x) {
    float t = fminf(fmaxf(x, -87.0f), 87.0f);
    float n = rintf(t * 1.4426950408889634f);
    float f = fmaf(n, -0.693145751953125f, t);
    f = fmaf(n, -1.4286067653e-06f, f);
    float p = 1.9841270e-04f;
    p = fmaf(p, f, 1.3888889e-03f);
    p = fmaf(p, f, 8.3333333e-03f);
    p = fmaf(p, f, 4.1666668e-02f);
    p = fmaf(p, f, 1.6666667e-01f);
    p = fmaf(p, f, 0.5f);
    p = fmaf(p, f, 1.0f);
    p = fmaf(p, f, 1.0f);
    int ni = (int)n;
    float sc = __int_as_float((ni + 127) << 23);
    return p * sc;
}
__device__ __forceinline__ float rcp_nr(float d) {
    float r;
    asm("rcp.approx.f32 %0, %1;" : "=f"(r) : "f"(d));
    r = fmaf(r, fmaf(-d, r, 1.0f), r);
    return r;
}
__device__ __forceinline__ float sig_p(float x) {
    return rcp_nr(1.0f + exp_p(-x));
}
__device__ __forceinline__ float tanh_p(float x) {
    float a = fabsf(x);
    float e = exp_p(-2.0f * a);
    float r = (1.0f - e) * rcp_nr(1.0f + e);
    return copysignf(r, x);
}

// ---------------- weight rearrangement ----------------
__global__ void prep_kernel(const float* __restrict__ W0f, const float* __restrict__ U0f,
                            const float* __restrict__ b0f, const float* __restrict__ W0b,
                            const float* __restrict__ U0b, const float* __restrict__ b0b,
                            const float* __restrict__ Wf, const float* __restrict__ Uf,
                            const float* __restrict__ bf, const float* __restrict__ Wb,
                            const float* __restrict__ Ub, const float* __restrict__ bb) {
    int idx0 = blockIdx.x * blockDim.x + threadIdx.x;
    int stride = gridDim.x * blockDim.x;
    for (int i = idx0; i < 3 * 2 * 256 * 1024; i += stride) {
        int j = i & 1023;
        int k = (i >> 10) & 255;
        int d = (i >> 18) & 1;
        int l = i >> 19;
        int u = j >> 2, g = j & 3;
        const float* Us = (l == 0) ? (d ? U0b : U0f)
                                   : (d ? Ub + (size_t)(l - 1) * 256 * 1024
                                        : Uf + (size_t)(l - 1) * 256 * 1024);
        g_Ure[l][d][k * 1024 + j] = Us[k * 1024 + g * 256 + u];
    }
    for (int i = idx0; i < 2 * 512 * 2048; i += stride) {
        int j2 = i & 2047;
        int k = (i >> 11) & 511;
        int l = i >> 20;
        int d = j2 >> 10;
        int j = j2 & 1023;
        int u = j >> 2, g = j & 3;
        const float* Ws = d ? Wb : Wf;
        g_Wcat[l][k * 2048 + j2] = Ws[(size_t)l * 512 * 1024 + k * 1024 + g * 256 + u];
    }
    for (int i = idx0; i < 2 * 2048; i += stride) {
        int j2 = i & 2047;
        int l = i >> 11;
        int d = j2 >> 10;
        int j = j2 & 1023;
        int u = j >> 2, g = j & 3;
        const float* bs = d ? bb : bf;
        g_bcat[l][j2] = bs[l * 1024 + g * 256 + u];
    }
    for (int i = idx0; i < 2 * 1024; i += stride) {
        int j = i & 1023;
        int d = i >> 10;
        int u = j >> 2, g = j & 3;
        g_W0re[d][j] = (d ? W0b : W0f)[g * 256 + u];
        g_b0re[d][j] = (d ? b0b : b0f)[g * 256 + u];
    }
}

// ---------------- per-layer init ----------------
__global__ void pre_recur_kernel(int zero_init) {
    int idx = blockIdx.x * blockDim.x + threadIdx.x;
    int stride = gridDim.x * blockDim.x;
    if (idx < 2) g_cnt[idx] = 0;
    float* hb = &g_hbuf[0][0][0];
    const float* sh = &g_stateH[0][0];
    float* sc = &g_stateC[0][0];
    for (int i = idx; i < 2 * UU * NB; i += stride) {
        hb[i] = zero_init ? 0.0f : sh[i];
        if (zero_init) sc[i] = 0.0f;
    }
}

// ---------------- recurrent kernel ----------------
// 128 CTAs (64/dir) x 256 threads. warp = 32-k chunk, lane = batch.
// h read straight from global into registers (coalesced LDG.32 per k) — no smem staging.
// Inner loop/k: pack + 4x bcast LDS.128 (U) + 8 FFMA2.
__global__ void __launch_bounds__(256, 1)
recur_kernel(const float* __restrict__ x0, float* __restrict__ dout,
             int layer, int is_last, int wstates) {
    __shared__ __align__(16) ulonglong2 U4s[UU * 4];   // [k][unit] (if,go)  16KB
    __shared__ __align__(16) ulonglong2 red2[32 * 32]; // [w*4+u][b]         16KB

    const int cta = blockIdx.x;
    const int dir = cta >> 6;
    const int uq = cta & 63;
    const int tid = threadIdx.x;
    const int w = tid >> 5;       // k-chunk
    const int b = tid & 31;       // batch lane

    // stage U slice: per k, 4 units x (if,go) float4
    {
        const float* Up = g_Ure[layer][dir];
        for (int i = tid; i < 1024; i += 256) {
            int k = i >> 2, u = i & 3;
            float4 v = *(const float4*)&Up[(size_t)k * 1024 + (uq * 4 + u) * 4];
            *(float4*)&U4s[k * 4 + u] = v;
        }
    }

    const int ur = tid >> 5;          // reducer unit (tid < 128)
    const int br = tid & 31;          // reducer batch
    float4 w0v = make_float4(0.f, 0.f, 0.f, 0.f), b0v = w0v;
    float c = 0.0f;
    if (tid < 128) {
        if (layer == 0) {
            w0v = *(const float4*)&g_W0re[dir][(uq * 4 + ur) * 4];
            b0v = *(const float4*)&g_b0re[dir][(uq * 4 + ur) * 4];
        }
        c = g_stateC[dir][(uq * 4 + ur) * 32 + br];
    }

    float* xout = is_last ? dout : (layer == 0 ? g_X1 : g_X2);
    unsigned* cntp = &g_cnt[dir];
    const float* xzbase = g_xz + dir * 1024 + uq * 16 + ur * 4;

    __syncthreads();

    for (int s = 0; s < TT; ++s) {
        const int t = dir ? (TT - 1 - s) : s;

        // reducers prefetch input preacts (hidden behind the poll)
        float4 xzv = make_float4(0.f, 0.f, 0.f, 0.f);
        if (tid < 128) {
            if (layer == 0) {
                float xv = __ldg(&x0[(size_t)br * TT + t]);
                xzv.x = fmaf(xv, w0v.x, b0v.x);
                xzv.y = fmaf(xv, w0v.y, b0v.y);
                xzv.z = fmaf(xv, w0v.z, b0v.z);
                xzv.w = fmaf(xv, w0v.w, b0v.w);
            } else {
                xzv = __ldg((const float4*)(xzbase + ((size_t)t * NB + br) * 2048));
            }
        }

        if (s > 0 && tid == 0) {
            const unsigned target = (unsigned)(64 * s);
            unsigned v;
            do {
                asm volatile("ld.acquire.gpu.global.u32 %0, [%1];"
                             : "=r"(v) : "l"(cntp) : "memory");
            } while (v < target);
        }
        __syncthreads();

        // load this warp's 32 h values straight into registers (coalesced)
        float hr[32];
        {
            const float* hrow = &g_hbuf[s & 1][dir][(w * 32) * 32 + b];
#pragma unroll
            for (int kk = 0; kk < 32; ++kk)
                hr[kk] = __ldcg(hrow + kk * 32);
        }

        // partial gate sums over this warp's 32-k slice, all 4 units
        unsigned long long acc[4][2];
#pragma unroll
        for (int u = 0; u < 4; ++u) { acc[u][0] = 0ULL; acc[u][1] = 0ULL; }
        {
            const ulonglong2* up = &U4s[(w * 32) * 4];
#pragma unroll
            for (int kk = 0; kk < 32; ++kk) {
                unsigned long long h2 = pack2(hr[kk]);
                ulonglong2 u0 = up[kk * 4 + 0];
                ulonglong2 u1 = up[kk * 4 + 1];
                ulonglong2 u2 = up[kk * 4 + 2];
                ulonglong2 u3 = up[kk * 4 + 3];
                fma2(acc[0][0], h2, u0.x); fma2(acc[0][1], h2, u0.y);
                fma2(acc[1][0], h2, u1.x); fma2(acc[1][1], h2, u1.y);
                fma2(acc[2][0], h2, u2.x); fma2(acc[2][1], h2, u2.y);
                fma2(acc[3][0], h2, u3.x); fma2(acc[3][1], h2, u3.y);
            }
        }
#pragma unroll
        for (int u = 0; u < 4; ++u) {
            ulonglong2 pv; pv.x = acc[u][0]; pv.y = acc[u][1];
            red2[(w * 4 + u) * 32 + b] = pv;
        }
        __syncthreads();

        if (tid < 128) {
            unsigned long long aif = pack2b(xzv.x, xzv.y);
            unsigned long long ago = pack2b(xzv.z, xzv.w);
#pragma unroll
            for (int w2 = 0; w2 < 8; ++w2) {
                ulonglong2 pv = red2[(w2 * 4 + ur) * 32 + br];
                add2(aif, pv.x);
                add2(ago, pv.y);
            }
            float2 fif = unpack2(aif), fgo = unpack2(ago);
            float zi = fif.x, zf = fif.y, zg = fgo.x, zo = fgo.y;

            c = sig_p(zf) * c + sig_p(zi) * tanh_p(zg);
            float h = sig_p(zo) * tanh_p(c);

            const int u = uq * 4 + ur;
            g_hbuf[(s + 1) & 1][dir][u * 32 + br] = h;
            asm volatile("bar.sync 1, 128;" ::: "memory");
            if (tid == 0) {
                asm volatile("red.release.gpu.global.add.u32 [%0], %1;"
                             :: "l"(cntp), "r"(1u) : "memory");
            }

            if (is_last)
                dout[((size_t)br * TT + t) * 512 + dir * 256 + u] = h;
            else
                xout[((size_t)t * NB + br) * 512 + dir * 256 + u] = h;

            if (s == TT - 1) {
                g_stateH[dir][u * 32 + br] = h;
                g_stateC[dir][u * 32 + br] = c;
                if (is_last && wstates) {
                    float* tail = dout + OUT_MAIN + (size_t)dir * 2 * NB * UU;
                    tail[br * UU + u] = h;
                    tail[NB * UU + br * UU + u] = c;
                }
            }
        }
    }
}

// ---------------- projection GEMM: C[65536,2048] = A[65536,512] @ W[512,2048] + bias ----
// grid: x = n-tile (16), y = m-tile (512) for L2 A-reuse. Prefetch distance 2.
#define GBM 128
#define GBN 128
#define GBK 16
#define AS_LD 264
#define AS_BUF (GBK * AS_LD)
#define WS_BUF (GBK * GBN)
#define GEMM_SMEM ((2 * AS_BUF + 2 * WS_BUF) * 4)

__global__ void __launch_bounds__(256)
gemm_kernel(int l) {
    extern __shared__ __align__(16) float gsm[];
    float* As = gsm;
    float* Ws = gsm + 2 * AS_BUF;

    const float* A = (l == 0) ? g_X1 : g_X2;
    const float* W = g_Wcat[l];
    const float* bias = g_bcat[l];
    float* C = g_xz;

    const int n0 = blockIdx.x * GBN;
    const int r0 = blockIdx.y * GBM;
    const int tid = threadIdx.x;
    const int tx = tid & 15;
    const int ty = tid >> 4;

    const int arow = tid >> 2;
    const int akq = tid & 3;
    const int wk = tid >> 5;
    const int wn = tid & 31;

    unsigned long long acc[8][4];
#pragma unroll
    for (int i = 0; i < 8; ++i)
#pragma unroll
        for (int j = 0; j < 4; ++j) acc[i][j] = 0ULL;

    const float* Ag = A + (size_t)(r0 + arow) * 512 + akq * 4;
    const float* Wg = W + (size_t)wk * 2048 + n0 + wn * 4;

    float4 ra0[2], ra1[2], rw0[2], rw1[2];
#pragma unroll
    for (int p = 0; p < 2; ++p) {
        ra0[p] = __ldg((const float4*)(Ag + p * 16));
        ra1[p] = __ldg((const float4*)(Ag + (size_t)64 * 512 + p * 16));
        rw0[p] = __ldg((const float4*)(Wg + (size_t)p * 16 * 2048));
        rw1[p] = __ldg((const float4*)(Wg + (size_t)p * 16 * 2048 + (size_t)8 * 2048));
    }

    for (int kt = 0; kt < 32; ++kt) {
        const int pp = kt & 1;
        float* as = As + pp * AS_BUF;
        float* ws = Ws + pp * WS_BUF;

        {
            float* d0 = as + (akq * 4 + 0) * AS_LD;
            float* d1 = as + (akq * 4 + 1) * AS_LD;
            float* d2 = as + (akq * 4 + 2) * AS_LD;
            float* d3 = as + (akq * 4 + 3) * AS_LD;
            int m0 = 2 * arow, m1 = 2 * (arow + 64);
            float4 a0 = ra0[pp], a1 = ra1[pp];
            d0[m0] = a0.x; d0[m0 + 1] = a0.x; d0[m1] = a1.x; d0[m1 + 1] = a1.x;
            d1[m0] = a0.y; d1[m0 + 1] = a0.y; d1[m1] = a1.y; d1[m1 + 1] = a1.y;
            d2[m0] = a0.z; d2[m0 + 1] = a0.z; d2[m1] = a1.z; d2[m1 + 1] = a1.z;
            d3[m0] = a0.w; d3[m0 + 1] = a0.w; d3[m1] = a1.w; d3[m1 + 1] = a1.w;
        }
        *(float4*)&ws[wk * GBN + wn * 4] = rw0[pp];
        *(float4*)&ws[(wk + 8) * GBN + wn * 4] = rw1[pp];
        __syncthreads();

        if (kt < 30) {
            ra0[pp] = __ldg((const float4*)(Ag + (kt + 2) * 16));
            ra1[pp] = __ldg((const float4*)(Ag + (size_t)64 * 512 + (kt + 2) * 16));
            rw0[pp] = __ldg((const float4*)(Wg + (size_t)(kt + 2) * 16 * 2048));
            rw1[pp] = __ldg((const float4*)(Wg + (size_t)(kt + 2) * 16 * 2048 + (size_t)8 * 2048));
        }

#pragma unroll
        for (int k = 0; k < GBK; ++k) {
            const float* ar = as + k * AS_LD + ty * 16;
            ulonglong2 a01 = *(const ulonglong2*)(ar);
            ulonglong2 a23 = *(const ulonglong2*)(ar + 4);
            ulonglong2 a45 = *(const ulonglong2*)(ar + 8);
            ulonglong2 a67 = *(const ulonglong2*)(ar + 12);
            const unsigned long long* wr =
                (const unsigned long long*)(ws + k * GBN + tx * 8);
            ulonglong2 w01 = *(const ulonglong2*)(wr);
            ulonglong2 w23 = *(const ulonglong2*)(wr + 2);

            unsigned long long am[8] = {a01.x, a01.y, a23.x, a23.y,
                                        a45.x, a45.y, a67.x, a67.y};
            unsigned long long wp[4] = {w01.x, w01.y, w23.x, w23.y};
#pragma unroll
            for (int m = 0; m < 8; ++m)
#pragma unroll
                for (int j = 0; j < 4; ++j) fma2(acc[m][j], am[m], wp[j]);
        }
        __syncthreads();
    }

    float4 bv0 = *(const float4*)&bias[n0 + tx * 8];
    float4 bv1 = *(const float4*)&bias[n0 + tx * 8 + 4];
#pragma unroll
    for (int m = 0; m < 8; ++m) {
        int row = r0 + ty * 8 + m;
        float2 p0 = unpack2(acc[m][0]);
        float2 p1 = unpack2(acc[m][1]);
        float2 p2 = unpack2(acc[m][2]);
        float2 p3 = unpack2(acc[m][3]);
        float4 o0 = make_float4(p0.x + bv0.x, p0.y + bv0.y, p1.x + bv0.z, p1.y + bv0.w);
        float4 o1 = make_float4(p2.x + bv1.x, p2.y + bv1.y, p3.x + bv1.z, p3.y + bv1.w);
        float* cp = &C[(size_t)row * 2048 + n0 + tx * 8];
        *(float4*)cp = o0;
        *(float4*)(cp + 4) = o1;
    }
}

// ---------------- launch ----------------
extern "C" void kernel_launch(void* const* d_in, const int* in_sizes, int n_in,
                              void* d_out, int out_size) {
    const float* inputs = (const float*)d_in[0];
    const float* W0f = (const float*)d_in[1];
    const float* U0f = (const float*)d_in[2];
    const float* b0f = (const float*)d_in[3];
    const float* W0b = (const float*)d_in[4];
    const float* U0b = (const float*)d_in[5];
    const float* b0b = (const float*)d_in[6];
    const float* Wf = (const float*)d_in[7];
    const float* Uf = (const float*)d_in[8];
    const float* bf = (const float*)d_in[9];
    const float* Wb = (const float*)d_in[10];
    const float* Ub = (const float*)d_in[11];
    const float* bb = (const float*)d_in[12];
    float* out = (float*)d_out;

    int wstates = ((size_t)out_size >= OUT_FULL) ? 1 : 0;

    cudaFuncSetAttribute(gemm_kernel, cudaFuncAttributeMaxDynamicSharedMemorySize,
                         GEMM_SMEM);

    prep_kernel<<<512, 256>>>(W0f, U0f, b0f, W0b, U0b, b0b, Wf, Uf, bf, Wb, Ub, bb);

    // layer 0
    pre_recur_kernel<<<64, 256>>>(1);
    recur_kernel<<<128, 256>>>(inputs, out, 0, 0, 0);

    // layer 1
    gemm_kernel<<<dim3(16, 512), 256, GEMM_SMEM>>>(0);
    pre_recur_kernel<<<64, 256>>>(0);
    recur_kernel<<<128, 256>>>(nullptr, out, 1, 0, 0);

    // layer 2
    gemm_kernel<<<dim3(16, 512), 256, GEMM_SMEM>>>(1);
    pre_recur_kernel<<<64, 256>>>(0);
    recur_kernel<<<128, 256>>>(nullptr, out, 2, 1, wstates);
}